// round 17
// baseline (speedup 1.0000x reference)
#include <cuda_runtime.h>
#include <cuda_fp16.h>
#include <math.h>
#include <stdint.h>

#define H    1024
#define NH   16
#define HD   64
#define FF   4096
#define SEQ  2048
#define BTOK 8192   // 4 * 2048 tokens
#define H3   3072   // fused QKV width
#define QT   128
#define NT   (SEQ / 64)

// ---------------------------------------------------------------------------
// Scratch (static __device__ globals: allocation-free rule)
// ---------------------------------------------------------------------------
__device__ __half g_qkv[(size_t)BTOK * H3];    // fp16 Q|K|V
__device__ float  g_svp[8 * 64 * 64];          // colsum(V) partials
__device__ float  g_ctx[BTOK * H];
__device__ float  g_x[BTOK * H];
__device__ __half g_xr[BTOK * H];              // fp16 LN1 output
__device__ __half g_hsr[BTOK * H];             // fp16 hidden_states
__device__ __half g_inter[(size_t)BTOK * FF];  // fp16 gelu output
__device__ float  g_ffn[BTOK * H];
__device__ __half g_wtqkv[(size_t)H3 * H];     // fp16 transposed weights
__device__ __half g_wt1[(size_t)H * FF];
__device__ __half g_wt2[(size_t)FF * H];
__device__ float  g_bqkv[H3];

// ---------------------------------------------------------------------------
// Helpers
// ---------------------------------------------------------------------------
__device__ __forceinline__ uint32_t smem_u32(const void* p) {
    uint32_t a;
    asm("{ .reg .u64 t; cvta.to.shared.u64 t, %1; cvt.u32.u64 %0, t; }"
        : "=r"(a) : "l"(p));
    return a;
}
__device__ __forceinline__ float gelu_exact(float x) {
    return 0.5f * x * (1.0f + erff(x * 0.70710678118654752f));
}

#define MMA_F16(ACC, A0, A1, A2, A3, B0, B1)                                   \
    asm volatile(                                                              \
        "mma.sync.aligned.m16n8k16.row.col.f32.f16.f16.f32 "                   \
        "{%0,%1,%2,%3}, {%4,%5,%6,%7}, {%8,%9}, {%0,%1,%2,%3};"                \
        : "+f"((ACC)[0]), "+f"((ACC)[1]), "+f"((ACC)[2]), "+f"((ACC)[3])       \
        : "r"(A0), "r"(A1), "r"(A2), "r"(A3), "r"(B0), "r"(B1))

#define LDM_X4(R0, R1, R2, R3, ADDR)                                           \
    asm volatile(                                                              \
        "ldmatrix.sync.aligned.m8n8.x4.shared.b16 {%0,%1,%2,%3}, [%4];"        \
        : "=r"(R0), "=r"(R1), "=r"(R2), "=r"(R3) : "r"(ADDR))

#define LDM_X4_T(R0, R1, R2, R3, ADDR)                                         \
    asm volatile(                                                              \
        "ldmatrix.sync.aligned.m8n8.x4.trans.shared.b16 {%0,%1,%2,%3}, [%4];"  \
        : "=r"(R0), "=r"(R1), "=r"(R2), "=r"(R3) : "r"(ADDR))

#define CP_ASYNC16(DST, SRC)                                                   \
    asm volatile("cp.async.cg.shared.global [%0], [%1], 16;"                   \
                 :: "r"(DST), "l"(SRC))
#define CP_COMMIT() asm volatile("cp.async.commit_group;" ::: "memory")
#define CP_WAIT0()  asm volatile("cp.async.wait_group 0;" ::: "memory")
#define CP_WAIT1()  asm volatile("cp.async.wait_group 1;" ::: "memory")
#define CP_WAIT2()  asm volatile("cp.async.wait_group 2;" ::: "memory")

#define BAR_PAIR(ID)                                                           \
    asm volatile("bar.sync %0, 64;" :: "r"(ID) : "memory")

// ---------------------------------------------------------------------------
// Prep kernels
// ---------------------------------------------------------------------------
__global__ __launch_bounds__(256)
void transpose_f16_k(const float* __restrict__ W, __half* __restrict__ Wt,
                     int K, int N)
{
    __shared__ float t[32][33];
    const int tx = threadIdx.x & 31;
    const int ty = threadIdx.x >> 5;
    const int n0 = blockIdx.x * 32;
    const int k0 = blockIdx.y * 32;
#pragma unroll
    for (int i = 0; i < 4; i++) {
        int r = ty + i * 8;
        t[r][tx] = W[(size_t)(k0 + r) * N + n0 + tx];
    }
    __syncthreads();
#pragma unroll
    for (int i = 0; i < 4; i++) {
        int r = ty + i * 8;
        Wt[(size_t)(n0 + r) * K + k0 + tx] = __float2half(t[tx][r]);
    }
}

__global__ __launch_bounds__(256)
void concat_bias_k(const float* __restrict__ bq, const float* __restrict__ bk,
                   const float* __restrict__ bv, float* __restrict__ o)
{
    int t = threadIdx.x + blockIdx.x * 256;
    if (t < H) o[t] = bq[t];
    else if (t < 2 * H) o[t] = bk[t - H];
    else o[t] = bv[t - 2 * H];
}

__global__ __launch_bounds__(256)
void cvt_f16_k(const float* __restrict__ x, __half* __restrict__ y)
{
    int i = blockIdx.x * 256 + threadIdx.x;
    float4 v = ((const float4*)x)[i];
    __half2* yo = (__half2*)y;
    yo[2 * i]     = __floats2half2_rn(v.x, v.y);
    yo[2 * i + 1] = __floats2half2_rn(v.z, v.w);
}

__global__ __launch_bounds__(64)
void sv_partial_k(const __half* __restrict__ QKV, float* __restrict__ SVP)
{
    const int bh = blockIdx.x, part = blockIdx.y;
    const int b = bh >> 4, h = bh & 15;
    const int d = threadIdx.x;
    const __half* src = QKV + (size_t)(b * SEQ + part * 256) * H3 + 2 * H + h * HD + d;
    float s = 0.0f;
    for (int kv = 0; kv < 256; kv++) s += __half2float(src[(size_t)kv * H3]);
    SVP[(part * 64 + bh) * 64 + d] = s;
}

// ---------------------------------------------------------------------------
// FP16 GEMM: mma.sync.m16n8k16 + ldmatrix + 4-stage cp.async pipeline.
// ---------------------------------------------------------------------------
#define BM 128
#define BN 128
#define PADKH 40                               // halfs per row (80B, cf-free)
#define GEMM_STAGE_B ((BM + BN) * PADKH * 2)   // 20480 bytes
#define GEMM_NSTG 4
#define GEMM_SMEM (GEMM_NSTG * GEMM_STAGE_B)   // 81920
#define GEMM_BOFF (BM * PADKH * 2)             // 10240

template <int EPI, int CO>
__global__ __launch_bounds__(256)
void mma_gemm(const __half* __restrict__ A, const __half* __restrict__ Bt,
              const float* __restrict__ bias, void* __restrict__ Cv,
              int M, int N, int K)
{
    extern __shared__ __align__(16) char gsm[];
    const uint32_t sBase = smem_u32(gsm);

    const int tid  = threadIdx.x;
    const int lane = tid & 31;
    const int wid  = tid >> 5;
    const int wm0  = (wid >> 1) * 32;
    const int wn0  = (wid & 1) * 64;
    const int r    = lane >> 2;
    const int c    = lane & 3;

    const int row0 = blockIdx.y * BM;
    const int col0 = blockIdx.x * BN;

    const int idxA0 = tid,       rowA0 = idxA0 >> 2, chA0 = idxA0 & 3;
    const int idxA1 = tid + 256, rowA1 = idxA1 >> 2, chA1 = idxA1 & 3;

    const __half* Ap0 = A  + (size_t)(row0 + rowA0) * K + chA0 * 8;
    const __half* Ap1 = A  + (size_t)(row0 + rowA1) * K + chA1 * 8;
    const __half* Bp0 = Bt + (size_t)(col0 + rowA0) * K + chA0 * 8;
    const __half* Bp1 = Bt + (size_t)(col0 + rowA1) * K + chA1 * 8;

    const uint32_t stsA0 = (uint32_t)((rowA0 * PADKH + chA0 * 8) * 2);
    const uint32_t stsA1 = (uint32_t)((rowA1 * PADKH + chA1 * 8) * 2);

    const uint32_t aLaneOff =
        (uint32_t)(((wm0 + (lane & 15)) * PADKH + (lane >> 4) * 8) * 2);
    const uint32_t bLaneOff = GEMM_BOFF +
        (uint32_t)(((wn0 + (lane & 7) + ((lane >> 4) & 1) * 8) * PADKH
                    + ((lane >> 3) & 1) * 8) * 2);

    float acc[2][8][4];
#pragma unroll
    for (int mt = 0; mt < 2; mt++)
#pragma unroll
        for (int nt = 0; nt < 8; nt++)
#pragma unroll
            for (int u = 0; u < 4; u++) acc[mt][nt][u] = 0.0f;

    const int NS = K / 32;

#pragma unroll
    for (int s = 0; s < 3; s++) {
        const uint32_t sb = sBase + s * GEMM_STAGE_B;
        const int k0 = s * 32;
        CP_ASYNC16(sb + stsA0, Ap0 + k0);
        CP_ASYNC16(sb + stsA1, Ap1 + k0);
        CP_ASYNC16(sb + GEMM_BOFF + stsA0, Bp0 + k0);
        CP_ASYNC16(sb + GEMM_BOFF + stsA1, Bp1 + k0);
        CP_COMMIT();
    }

    int buf = 0;
    for (int s = 0; s < NS; s++) {
        if (s + 1 >= NS) CP_WAIT0();
        else if (s + 2 >= NS) CP_WAIT1();
        else CP_WAIT2();
        __syncthreads();

        const uint32_t sb = sBase + buf * GEMM_STAGE_B;

#pragma unroll
        for (int ks = 0; ks < 2; ks++) {
            const uint32_t ko = ks * 32;
            uint32_t af[2][4];
            LDM_X4(af[0][0], af[0][1], af[0][2], af[0][3],
                   sb + aLaneOff + ko);
            LDM_X4(af[1][0], af[1][1], af[1][2], af[1][3],
                   sb + aLaneOff + 16 * PADKH * 2 + ko);
#pragma unroll
            for (int np = 0; np < 4; np++) {
                uint32_t b0, b1, b2, b3;
                LDM_X4(b0, b1, b2, b3, sb + bLaneOff + np * (16 * PADKH * 2) + ko);
                MMA_F16(acc[0][2 * np],     af[0][0], af[0][1], af[0][2], af[0][3], b0, b1);
                MMA_F16(acc[1][2 * np],     af[1][0], af[1][1], af[1][2], af[1][3], b0, b1);
                MMA_F16(acc[0][2 * np + 1], af[0][0], af[0][1], af[0][2], af[0][3], b2, b3);
                MMA_F16(acc[1][2 * np + 1], af[1][0], af[1][1], af[1][2], af[1][3], b2, b3);
            }
        }

        if (s + 3 < NS) {
            const int nb = (buf + 3) & 3;
            const uint32_t nsb = sBase + nb * GEMM_STAGE_B;
            const int k0 = (s + 3) * 32;
            CP_ASYNC16(nsb + stsA0, Ap0 + k0);
            CP_ASYNC16(nsb + stsA1, Ap1 + k0);
            CP_ASYNC16(nsb + GEMM_BOFF + stsA0, Bp0 + k0);
            CP_ASYNC16(nsb + GEMM_BOFF + stsA1, Bp1 + k0);
            CP_COMMIT();
        }
        buf = (buf + 1) & 3;
    }

#pragma unroll
    for (int mt = 0; mt < 2; mt++) {
        const int rowA = row0 + wm0 + mt * 16 + r;
#pragma unroll
        for (int nt = 0; nt < 8; nt++) {
            const int col = col0 + wn0 + nt * 8 + 2 * c;
            const float bz0 = bias[col];
            const float bz1 = bias[col + 1];
            float v0 = acc[mt][nt][0] + bz0;
            float v1 = acc[mt][nt][1] + bz1;
            float v2 = acc[mt][nt][2] + bz0;
            float v3 = acc[mt][nt][3] + bz1;
            if (EPI == 1) {
                v0 = fminf(fmaxf(gelu_exact(v0), -1e9f), 1e9f);
                v1 = fminf(fmaxf(gelu_exact(v1), -1e9f), 1e9f);
                v2 = fminf(fmaxf(gelu_exact(v2), -1e9f), 1e9f);
                v3 = fminf(fmaxf(gelu_exact(v3), -1e9f), 1e9f);
            }
            if (CO) {
                __half* Ch = (__half*)Cv;
                *(__half2*)(Ch + (size_t)rowA * N + col) =
                    __floats2half2_rn(v0, v1);
                *(__half2*)(Ch + (size_t)(rowA + 8) * N + col) =
                    __floats2half2_rn(v2, v3);
            } else {
                float* Cf = (float*)Cv;
                *(float2*)(Cf + (size_t)rowA * N + col)       = make_float2(v0, v1);
                *(float2*)(Cf + (size_t)(rowA + 8) * N + col) = make_float2(v2, v3);
            }
        }
    }
}

// ---------------------------------------------------------------------------
// Flash attention, fp16 MMA: 128-query tiles, 512 threads = 16 warps.
// Register-resident softmax: scores never staged to smem; warp pairs
// (2i, 2i+1) own 16 q-rows and synchronize via named 64-thread barriers.
// Q/K/V fp16 via cp.async; V fragments via ldmatrix.trans.
// ---------------------------------------------------------------------------
#define QSTR 72                       // half stride for Q/K/V/P tiles (144B)
#define QBYTES (QT * QSTR * 2)        // 18432
#define KTILEB (64 * QSTR * 2)        // 9216 per tile
#define OFFB_K  18432
#define OFFB_V  (OFFB_K + 2 * KTILEB)        // 36864
#define OFFB_P  (OFFB_V + 2 * KTILEB)        // 55296 (fp16 probs 128x72)
#define OFFB_ST (OFFB_P + QBYTES)            // 73728 stats
// stats: m[128], l[128], wmax[128][2], wsum[128][2], sv[64]
#define ATTN_SMEM (OFFB_ST + (QT + QT + 2 * QT + 2 * QT + 64) * 4)

__global__ __launch_bounds__(512)
void attn_mma_kernel(const __half* __restrict__ QKV,
                     const float* __restrict__ SVP, float* __restrict__ O)
{
    extern __shared__ __align__(16) char smc[];
    __half* Psh   = (__half*)(smc + OFFB_P);
    float* m_s    = (float*)(smc + OFFB_ST);
    float* l_s    = m_s + QT;
    float* wmax_s = l_s + QT;          // [row][warpInPair]
    float* wsum_s = wmax_s + 2 * QT;
    float* sv_s   = wsum_s + 2 * QT;

    const int tid  = threadIdx.x;
    const int lane = tid & 31;
    const int wid  = tid >> 5;           // 0..15
    const int wq0  = (wid >> 1) * 16;
    const int wn0  = (wid & 1) * 32;
    const int wp   = wid & 1;
    const int pairId = (wid >> 1) + 1;   // named barriers 1..8
    const int r    = lane >> 2;
    const int c    = lane & 3;

    const int bh = blockIdx.y;
    const int b  = bh >> 4;
    const int h  = bh & 15;
    const int qstart = blockIdx.x * QT;
    const size_t rowbase = (size_t)b * SEQ;
    const __half* Qg = QKV + (size_t)h * HD;
    const __half* Kg = Qg + H;
    const __half* Vg = Qg + 2 * H;
    const size_t obase = (size_t)b * SEQ * H + (size_t)h * HD;

    const uint32_t sQ = smem_u32(smc);
    const uint32_t sK = sQ + OFFB_K;
    const uint32_t sV = sQ + OFFB_V;
    const uint32_t sP = sQ + OFFB_P;

    // ldmatrix lane offsets
    const uint32_t qLane = sQ +
        (uint32_t)(((wq0 + (lane & 15)) * QSTR + (lane >> 4) * 8) * 2);
    const uint32_t pLane = sP +
        (uint32_t)(((wq0 + (lane & 15)) * QSTR + (lane >> 4) * 8) * 2);
    const uint32_t kLaneOff =
        (uint32_t)(((wn0 + (lane & 7) + ((lane >> 4) & 1) * 8) * QSTR
                    + ((lane >> 3) & 1) * 8) * 2);
    const uint32_t vLaneOff =
        (uint32_t)((((lane & 7) + ((lane >> 3) & 1) * 8) * QSTR
                    + wn0 + ((lane >> 4) & 1) * 8) * 2);

    // ---- prologue: Q + KV tiles 0,1 ----
#pragma unroll
    for (int it = 0; it < 2; it++) {
        const int idx = tid + it * 512;
        const int row = idx >> 3, ch = idx & 7;
        CP_ASYNC16(sQ + (uint32_t)((row * QSTR + ch * 8) * 2),
                   Qg + (rowbase + qstart + row) * H3 + ch * 8);
    }
    {
        const int row = tid >> 3, ch = tid & 7;
        const uint32_t dsto = (uint32_t)((row * QSTR + ch * 8) * 2);
        CP_ASYNC16(sK + dsto, Kg + (rowbase + row) * H3 + ch * 8);
        CP_ASYNC16(sV + dsto, Vg + (rowbase + row) * H3 + ch * 8);
    }
    CP_COMMIT();
    {
        const int row = tid >> 3, ch = tid & 7;
        const uint32_t dsto = (uint32_t)((row * QSTR + ch * 8) * 2) + KTILEB;
        CP_ASYNC16(sK + dsto, Kg + (rowbase + 64 + row) * H3 + ch * 8);
        CP_ASYNC16(sV + dsto, Vg + (rowbase + 64 + row) * H3 + ch * 8);
    }
    CP_COMMIT();
    CP_WAIT1();

    if (tid < QT) { m_s[tid] = -1e30f; l_s[tid] = 0.0f; }
    if (tid < 64) {
        float s = 0.0f;
#pragma unroll
        for (int p = 0; p < 8; p++) s += SVP[(p * 64 + bh) * 64 + tid];
        sv_s[tid] = 1e-9f * s;
    }

    float oacc[4][4];
#pragma unroll
    for (int nt = 0; nt < 4; nt++)
#pragma unroll
        for (int u = 0; u < 4; u++) oacc[nt][u] = 0.0f;

    const int row0 = wq0 + r, row1 = row0 + 8;

    __syncthreads();

    for (int kt = 0; kt < NT; kt++) {
        const int cur = kt & 1;
        const uint32_t kCur = sK + cur * KTILEB + kLaneOff;
        const uint32_t vCur = sV + cur * KTILEB + vLaneOff;

        // ---- S = Q K^T -> registers ----
        float sacc[4][4];
#pragma unroll
        for (int nt = 0; nt < 4; nt++)
#pragma unroll
            for (int u = 0; u < 4; u++) sacc[nt][u] = 0.0f;

#pragma unroll
        for (int ks = 0; ks < 4; ks++) {
            const uint32_t ko = ks * 32;
            uint32_t a0, a1, a2, a3;
            LDM_X4(a0, a1, a2, a3, qLane + ko);
#pragma unroll
            for (int np = 0; np < 2; np++) {
                uint32_t b0, b1, b2, b3;
                LDM_X4(b0, b1, b2, b3, kCur + np * (16 * QSTR * 2) + ko);
                MMA_F16(sacc[2 * np],     a0, a1, a2, a3, b0, b1);
                MMA_F16(sacc[2 * np + 1], a0, a1, a2, a3, b2, b3);
            }
        }

        // ---- register softmax (warp-pair cooperative) ----
        float mx0 = -1e30f, mx1 = -1e30f;
#pragma unroll
        for (int nt = 0; nt < 4; nt++) {
            sacc[nt][0] = fminf(fmaxf(sacc[nt][0] * 0.125f, -1e9f), 1e9f);
            sacc[nt][1] = fminf(fmaxf(sacc[nt][1] * 0.125f, -1e9f), 1e9f);
            sacc[nt][2] = fminf(fmaxf(sacc[nt][2] * 0.125f, -1e9f), 1e9f);
            sacc[nt][3] = fminf(fmaxf(sacc[nt][3] * 0.125f, -1e9f), 1e9f);
            mx0 = fmaxf(mx0, fmaxf(sacc[nt][0], sacc[nt][1]));
            mx1 = fmaxf(mx1, fmaxf(sacc[nt][2], sacc[nt][3]));
        }
        mx0 = fmaxf(mx0, __shfl_xor_sync(0xffffffffu, mx0, 1));
        mx0 = fmaxf(mx0, __shfl_xor_sync(0xffffffffu, mx0, 2));
        mx1 = fmaxf(mx1, __shfl_xor_sync(0xffffffffu, mx1, 1));
        mx1 = fmaxf(mx1, __shfl_xor_sync(0xffffffffu, mx1, 2));
        if (c == 0) {
            wmax_s[row0 * 2 + wp] = mx0;
            wmax_s[row1 * 2 + wp] = mx1;
        }
        BAR_PAIR(pairId);

        const float mo0 = m_s[row0], mo1 = m_s[row1];
        const float mt0 = fmaxf(fmaxf(wmax_s[row0 * 2], wmax_s[row0 * 2 + 1]), mo0);
        const float mt1 = fmaxf(fmaxf(wmax_s[row1 * 2], wmax_s[row1 * 2 + 1]), mo1);
        const float sc0 = __expf(mo0 - mt0);
        const float sc1 = __expf(mo1 - mt1);

        float sum0 = 0.0f, sum1 = 0.0f;
#pragma unroll
        for (int nt = 0; nt < 4; nt++) {
            const float e00 = __expf(sacc[nt][0] - mt0);
            const float e01 = __expf(sacc[nt][1] - mt0);
            const float e10 = __expf(sacc[nt][2] - mt1);
            const float e11 = __expf(sacc[nt][3] - mt1);
            sum0 += e00 + e01;
            sum1 += e10 + e11;
            const int col = wn0 + nt * 8 + 2 * c;
            *(__half2*)&Psh[row0 * QSTR + col] = __floats2half2_rn(e00, e01);
            *(__half2*)&Psh[row1 * QSTR + col] = __floats2half2_rn(e10, e11);
        }
        sum0 += __shfl_xor_sync(0xffffffffu, sum0, 1);
        sum0 += __shfl_xor_sync(0xffffffffu, sum0, 2);
        sum1 += __shfl_xor_sync(0xffffffffu, sum1, 1);
        sum1 += __shfl_xor_sync(0xffffffffu, sum1, 2);
        if (c == 0) {
            wsum_s[row0 * 2 + wp] = sum0;
            wsum_s[row1 * 2 + wp] = sum1;
        }
        BAR_PAIR(pairId);

        if (wp == 0 && c == 0) {
            l_s[row0] = l_s[row0] * sc0 + wsum_s[row0 * 2] + wsum_s[row0 * 2 + 1];
            m_s[row0] = mt0;
            l_s[row1] = l_s[row1] * sc1 + wsum_s[row1 * 2] + wsum_s[row1 * 2 + 1];
            m_s[row1] = mt1;
        }

        // rescale accumulators
#pragma unroll
        for (int nt = 0; nt < 4; nt++) {
            oacc[nt][0] *= sc0; oacc[nt][1] *= sc0;
            oacc[nt][2] *= sc1; oacc[nt][3] *= sc1;
        }

        // ---- O += P V (V fragments via ldmatrix.trans) ----
#pragma unroll
        for (int ks = 0; ks < 4; ks++) {
            uint32_t a0, a1, a2, a3;
            LDM_X4(a0, a1, a2, a3, pLane + ks * 32);
#pragma unroll
            for (int np = 0; np < 2; np++) {
                uint32_t b0, b1, b2, b3;
                LDM_X4_T(b0, b1, b2, b3,
                         vCur + ks * (16 * QSTR * 2) + np * 32);
                MMA_F16(oacc[2 * np],     a0, a1, a2, a3, b0, b1);
                MMA_F16(oacc[2 * np + 1], a0, a1, a2, a3, b2, b3);
            }
        }
        __syncthreads();   // all reads of buffer cur done

        // prefetch tile kt+2 into buffer cur
        if (kt + 2 < NT) {
            const int kstart = (kt + 2) * 64;
            const int row = tid >> 3, ch = tid & 7;
            const uint32_t dsto =
                (uint32_t)((row * QSTR + ch * 8) * 2) + cur * KTILEB;
            CP_ASYNC16(sK + dsto, Kg + (rowbase + kstart + row) * H3 + ch * 8);
            CP_ASYNC16(sV + dsto, Vg + (rowbase + kstart + row) * H3 + ch * 8);
            CP_COMMIT();
            CP_WAIT1();
        } else {
            CP_WAIT0();
        }
        __syncthreads();
    }

    // epilogue
    {
        const float linv0 = 1.0f / l_s[row0];
        const float linv1 = 1.0f / l_s[row1];
        const int row = qstart + wq0 + r;
#pragma unroll
        for (int nt = 0; nt < 4; nt++) {
            const int col = wn0 + nt * 8 + 2 * c;
            const float e0 = sv_s[col], e1 = sv_s[col + 1];
            float2 o0 = make_float2(oacc[nt][0] * linv0 + e0,
                                    oacc[nt][1] * linv0 + e1);
            float2 o1 = make_float2(oacc[nt][2] * linv1 + e0,
                                    oacc[nt][3] * linv1 + e1);
            *(float2*)&O[obase + (size_t)row * H + col]       = o0;
            *(float2*)&O[obase + (size_t)(row + 8) * H + col] = o1;
        }
    }
}

// ---------------------------------------------------------------------------
// Fused residual-add + LayerNorm; optional fp16 copy of the output.
// ---------------------------------------------------------------------------
template <int WR>
__global__ __launch_bounds__(256)
void add_ln_kernel(const float* __restrict__ A, const float* __restrict__ Bres,
                   const float* __restrict__ gam, const float* __restrict__ bet,
                   float* __restrict__ out, __half* __restrict__ out_r)
{
    const int row = blockIdx.x;
    const int tid = threadIdx.x;
    const float4 va = ((const float4*)(A    + (size_t)row * H))[tid];
    const float4 vb = ((const float4*)(Bres + (size_t)row * H))[tid];
    float x0 = va.x + vb.x, x1 = va.y + vb.y, x2 = va.z + vb.z, x3 = va.w + vb.w;

    __shared__ float red[8];
    __shared__ float s_mu, s_rstd;

    float s = x0 + x1 + x2 + x3;
#pragma unroll
    for (int o = 16; o; o >>= 1) s += __shfl_down_sync(0xffffffffu, s, o);
    if ((tid & 31) == 0) red[tid >> 5] = s;
    __syncthreads();
    if (tid == 0) {
        float t = 0.f;
#pragma unroll
        for (int i = 0; i < 8; i++) t += red[i];
        s_mu = t * (1.0f / H);
    }
    __syncthreads();
    const float mu = s_mu;
    float d0 = x0 - mu, d1 = x1 - mu, d2 = x2 - mu, d3 = x3 - mu;
    float ss = d0 * d0 + d1 * d1 + d2 * d2 + d3 * d3;
#pragma unroll
    for (int o = 16; o; o >>= 1) ss += __shfl_down_sync(0xffffffffu, ss, o);
    __syncthreads();
    if ((tid & 31) == 0) red[tid >> 5] = ss;
    __syncthreads();
    if (tid == 0) {
        float t = 0.f;
#pragma unroll
        for (int i = 0; i < 8; i++) t += red[i];
        s_rstd = rsqrtf(t * (1.0f / H) + 1e-12f);
    }
    __syncthreads();
    const float rstd = s_rstd;

    const float4 g4 = ((const float4*)gam)[tid];
    const float4 b4 = ((const float4*)bet)[tid];
    float4 o;
    o.x = d0 * rstd * g4.x + b4.x;
    o.y = d1 * rstd * g4.y + b4.y;
    o.z = d2 * rstd * g4.z + b4.z;
    o.w = d3 * rstd * g4.w + b4.w;
    ((float4*)(out + (size_t)row * H))[tid] = o;
    if (WR) {
        __half2* orh = (__half2*)(out_r + (size_t)row * H);
        orh[2 * tid]     = __floats2half2_rn(o.x, o.y);
        orh[2 * tid + 1] = __floats2half2_rn(o.z, o.w);
    }
}

// ---------------------------------------------------------------------------
// Launch
// ---------------------------------------------------------------------------
extern "C" void kernel_launch(void* const* d_in, const int* in_sizes, int n_in,
                              void* d_out, int out_size)
{
    const float* hs   = (const float*)d_in[0];
    const float* Wq   = (const float*)d_in[1];
    const float* bq   = (const float*)d_in[2];
    const float* Wk   = (const float*)d_in[3];
    const float* bk   = (const float*)d_in[4];
    const float* Wv   = (const float*)d_in[5];
    const float* bv   = (const float*)d_in[6];
    const float* ln1g = (const float*)d_in[7];
    const float* ln1b = (const float*)d_in[8];
    const float* W1   = (const float*)d_in[9];
    const float* b1   = (const float*)d_in[10];
    const float* W2   = (const float*)d_in[11];
    const float* b2   = (const float*)d_in[12];
    const float* ln2g = (const float*)d_in[13];
    const float* ln2b = (const float*)d_in[14];
    float* out = (float*)d_out;

    static __half *pqkv = nullptr, *pxr = nullptr, *phsr = nullptr,
                  *pinter = nullptr, *pwqkv = nullptr, *pwt1 = nullptr,
                  *pwt2 = nullptr;
    static float *psvp = nullptr, *pctx = nullptr, *px = nullptr,
                 *pffn = nullptr, *pbqkv = nullptr;
    static cudaStream_t st1 = nullptr, st2 = nullptr;
    static cudaEvent_t ev0, ev1, ev2;
    if (!pqkv) {  // first call is the (uncaptured) correctness run
        cudaGetSymbolAddress((void**)&pqkv,   g_qkv);
        cudaGetSymbolAddress((void**)&psvp,   g_svp);
        cudaGetSymbolAddress((void**)&pctx,   g_ctx);
        cudaGetSymbolAddress((void**)&px,     g_x);
        cudaGetSymbolAddress((void**)&pxr,    g_xr);
        cudaGetSymbolAddress((void**)&phsr,   g_hsr);
        cudaGetSymbolAddress((void**)&pinter, g_inter);
        cudaGetSymbolAddress((void**)&pffn,   g_ffn);
        cudaGetSymbolAddress((void**)&pwqkv,  g_wtqkv);
        cudaGetSymbolAddress((void**)&pwt1,   g_wt1);
        cudaGetSymbolAddress((void**)&pwt2,   g_wt2);
        cudaGetSymbolAddress((void**)&pbqkv,  g_bqkv);
        cudaStreamCreateWithFlags(&st1, cudaStreamNonBlocking);
        cudaStreamCreateWithFlags(&st2, cudaStreamNonBlocking);
        cudaEventCreateWithFlags(&ev0, cudaEventDisableTiming);
        cudaEventCreateWithFlags(&ev1, cudaEventDisableTiming);
        cudaEventCreateWithFlags(&ev2, cudaEventDisableTiming);
        cudaFuncSetAttribute(attn_mma_kernel,
                             cudaFuncAttributeMaxDynamicSharedMemorySize, ATTN_SMEM);
        cudaFuncSetAttribute(mma_gemm<0, 1>,
                             cudaFuncAttributeMaxDynamicSharedMemorySize, GEMM_SMEM);
        cudaFuncSetAttribute(mma_gemm<1, 1>,
                             cudaFuncAttributeMaxDynamicSharedMemorySize, GEMM_SMEM);
        cudaFuncSetAttribute(mma_gemm<0, 0>,
                             cudaFuncAttributeMaxDynamicSharedMemorySize, GEMM_SMEM);
    }

    // fork: FFN weight transposes on side streams (join before FFN1)
    cudaEventRecord(ev0, 0);
    cudaStreamWaitEvent(st1, ev0, 0);
    cudaStreamWaitEvent(st2, ev0, 0);
    transpose_f16_k<<<dim3(FF / 32, H / 32), 256, 0, st1>>>(W1, pwt1, H, FF);
    transpose_f16_k<<<dim3(H / 32, FF / 32), 256, 0, st2>>>(W2, pwt2, FF, H);
    cudaEventRecord(ev1, st1);
    cudaEventRecord(ev2, st2);

    // critical-path prep (QKV-related only)
    transpose_f16_k<<<dim3(H / 32, H / 32), 256>>>(Wq, pwqkv,             H, H);
    transpose_f16_k<<<dim3(H / 32, H / 32), 256>>>(Wk, pwqkv + H * H,     H, H);
    transpose_f16_k<<<dim3(H / 32, H / 32), 256>>>(Wv, pwqkv + 2 * H * H, H, H);
    concat_bias_k<<<H3 / 256, 256>>>(bq, bk, bv, pbqkv);
    cvt_f16_k<<<BTOK * H / 1024, 256>>>(hs, phsr);

    // fused QKV projection -> fp16 output
    mma_gemm<0, 1><<<dim3(H3 / 128, BTOK / 128), 256, GEMM_SMEM>>>(
        phsr, pwqkv, pbqkv, pqkv, BTOK, H3, H);
    // colsum(V) partials
    sv_partial_k<<<dim3(64, 8), 64>>>(pqkv, psvp);
    // attention -> ctx (fp32)
    attn_mma_kernel<<<dim3(SEQ / QT, 4 * NH), 512, ATTN_SMEM>>>(pqkv, psvp, pctx);
    // residual + LN1 -> x (+ fp16 copy for FFN1)
    add_ln_kernel<1><<<BTOK, 256>>>(hs, pctx, ln1g, ln1b, px, pxr);

    // join the FFN weight branches
    cudaStreamWaitEvent(0, ev1, 0);
    cudaStreamWaitEvent(0, ev2, 0);

    // FFN1 (gelu output fp16)
    mma_gemm<1, 1><<<dim3(FF / 128, BTOK / 128), 256, GEMM_SMEM>>>(
        pxr, pwt1, b1, pinter, BTOK, FF, H);
    // FFN2 (fp32 output)
    mma_gemm<0, 0><<<dim3(H / 128, BTOK / 128), 256, GEMM_SMEM>>>(
        pinter, pwt2, b2, pffn, BTOK, H, FF);
    // residual + LN2 -> out
    add_ln_kernel<0><<<BTOK, 256>>>(pffn, px, ln2g, ln2b, out, nullptr);
}